// round 3
// baseline (speedup 1.0000x reference)
#include <cuda_runtime.h>

// DiffKS: fused time-varying FIR (order 6) + time-varying all-pole IIR (order 2).
//   x[t]  = y[t] + sum_{k=1..6} Ae[b,t,k-1] * y[t-k]     (zero history)
//   out[t]= x[t] - sum_{k=1..2} Al[b,t,k-1] * out[t-k]   (zero initial state)
//
// Per-(batch,chunk) thread with warmup (contractive IIR: |a|<=0.25 -> 0.64/step,
// WARM=32 -> 6e-7 state error; FIR history self-heals in 6 samples; chunk 0 is
// made exact by an explicit state reset at t==0).
//
// R2 lesson: l1tex wavefront-bound (uncoalesced per-thread LDG.128 = 32
// wavefronts/instr). This version: lockstep phases with block-cooperative
// COALESCED global loads staged through shared memory (odd float4 pitches ->
// conflict-free LDS), register-prefetch double buffering, 1 sync per phase.

#define BATCH 48
#define TLEN  88200
#define CHUNK 112
#define WARM  32
#define G     8
#define CPB   128                     // chunks (threads) per block
#define NCH   788                     // ceil(TLEN/CHUNK)
#define BPR   7                       // ceil(NCH/CPB) blocks per row
#define PHASES ((CHUNK + WARM) / G)   // 18

// smem regions in float4 units (windows padded to odd pitches: 3, 13, 5)
#define YSZ   (CPB * 3)               // 384
#define AESZ  (CPB * 13)              // 1664
#define ALSZ  (CPB * 5)               // 640
#define BUF   (YSZ + AESZ + ALSZ)     // 2688 float4
#define SMEM_BYTES (2 * BUF * 16)     // 86016

__global__ void __launch_bounds__(CPB, 2)
diffks_kernel(const float* __restrict__ y,
              const float* __restrict__ Ae,
              const float* __restrict__ Al,
              float* __restrict__ out)
{
    extern __shared__ float4 smem[];
    const int tid  = threadIdx.x;
    const int b    = blockIdx.x / BPR;
    const int seg  = blockIdx.x % BPR;
    const int cbase = seg * CPB;

    const float4* yb4 = reinterpret_cast<const float4*>(y  + (size_t)b * TLEN);
    const float4* ae4 = reinterpret_cast<const float4*>(Ae + (size_t)b * TLEN * 6);
    const float4* al4 = reinterpret_cast<const float4*>(Al + (size_t)b * TLEN * 2);
    float*        ob  = out + (size_t)b * TLEN;

    // ---- flat cooperative-load descriptors (consecutive tid -> consecutive f4) ----
    int t_y[2],  k_y[2],  si_y[2];
    int t_ae[12], k_ae[12], si_ae[12];
    int t_al[4], k_al[4], si_al[4];
    #pragma unroll
    for (int j = 0; j < 2; j++) {
        int f = tid + CPB * j; int w = f >> 1; int k = f & 1;
        t_y[j] = (cbase + w) * CHUNK - WARM; k_y[j] = k; si_y[j] = w * 3 + k;
    }
    #pragma unroll
    for (int j = 0; j < 12; j++) {
        int f = tid + CPB * j; int w = f / 12; int k = f - 12 * w;
        t_ae[j] = (cbase + w) * CHUNK - WARM; k_ae[j] = k; si_ae[j] = YSZ + w * 13 + k;
    }
    #pragma unroll
    for (int j = 0; j < 4; j++) {
        int f = tid + CPB * j; int w = f >> 2; int k = f & 3;
        t_al[j] = (cbase + w) * CHUNK - WARM; k_al[j] = k; si_al[j] = YSZ + AESZ + w * 5 + k;
    }

    // ---- prefetch phase 0 into registers (clamped to valid range) ----
    float4 ry[2], rae[12], ral[4];
    #pragma unroll
    for (int j = 0; j < 2; j++) {
        int tc = min(max(t_y[j], 0), TLEN - G);
        ry[j] = yb4[(tc >> 2) + k_y[j]];
    }
    #pragma unroll
    for (int j = 0; j < 12; j++) {
        int tc = min(max(t_ae[j], 0), TLEN - G);
        rae[j] = ae4[(tc >> 1) * 3 + k_ae[j]];
    }
    #pragma unroll
    for (int j = 0; j < 4; j++) {
        int tc = min(max(t_al[j], 0), TLEN - G);
        ral[j] = al4[(tc >> 1) + k_al[j]];
    }

    const int start    = (cbase + tid) * CHUNK;
    const int my_rd_y  = tid * 3;
    const int my_rd_ae = YSZ + tid * 13;
    const int my_rd_al = YSZ + AESZ + tid * 5;

    float h0 = 0, h1 = 0, h2 = 0, h3 = 0, h4 = 0, h5 = 0;
    float s1 = 0, s2 = 0;

    for (int p = 0; p < PHASES; p++) {
        float4* buf = smem + (p & 1) * BUF;

        // stage current phase regs -> smem
        #pragma unroll
        for (int j = 0; j < 2; j++)  buf[si_y[j]]  = ry[j];
        #pragma unroll
        for (int j = 0; j < 12; j++) buf[si_ae[j]] = rae[j];
        #pragma unroll
        for (int j = 0; j < 4; j++)  buf[si_al[j]] = ral[j];
        __syncthreads();

        // prefetch next phase (overlaps compute below)
        if (p + 1 < PHASES) {
            #pragma unroll
            for (int j = 0; j < 2; j++) {
                t_y[j] += G;
                int tc = min(max(t_y[j], 0), TLEN - G);
                ry[j] = yb4[(tc >> 2) + k_y[j]];
            }
            #pragma unroll
            for (int j = 0; j < 12; j++) {
                t_ae[j] += G;
                int tc = min(max(t_ae[j], 0), TLEN - G);
                rae[j] = ae4[(tc >> 1) * 3 + k_ae[j]];
            }
            #pragma unroll
            for (int j = 0; j < 4; j++) {
                t_al[j] += G;
                int tc = min(max(t_al[j], 0), TLEN - G);
                ral[j] = al4[(tc >> 1) + k_al[j]];
            }
        }

        // compute G=8 samples from smem (conflict-free LDS.128, odd pitches)
        const int tbase = start - WARM + p * G;
        #pragma unroll
        for (int g = 0; g < 2; g++) {
            float4 y4 = buf[my_rd_y + g];
            float4 e0 = buf[my_rd_ae + 6 * g + 0];
            float4 e1 = buf[my_rd_ae + 6 * g + 1];
            float4 e2 = buf[my_rd_ae + 6 * g + 2];
            float4 e3 = buf[my_rd_ae + 6 * g + 3];
            float4 e4 = buf[my_rd_ae + 6 * g + 4];
            float4 e5 = buf[my_rd_ae + 6 * g + 5];
            float4 l0 = buf[my_rd_al + 2 * g + 0];
            float4 l1 = buf[my_rd_al + 2 * g + 1];

            int t = tbase + 4 * g;
            if (t == 0) {            // chunk 0: exact zero state at sequence start
                h0 = h1 = h2 = h3 = h4 = h5 = 0.f;
                s1 = s2 = 0.f;
            }

            float4 o4;
            float x, yo;

            // t+0 : Ae = e0.xyzw, e1.xy ; Al = l0.xy
            x  = y4.x + e0.x*h0 + e0.y*h1 + e0.z*h2 + e0.w*h3 + e1.x*h4 + e1.y*h5;
            yo = x - l0.x*s1 - l0.y*s2;
            s2 = s1; s1 = yo; o4.x = yo;
            h5 = h4; h4 = h3; h3 = h2; h2 = h1; h1 = h0; h0 = y4.x;

            // t+1 : Ae = e1.zw, e2.xyzw ; Al = l0.zw
            x  = y4.y + e1.z*h0 + e1.w*h1 + e2.x*h2 + e2.y*h3 + e2.z*h4 + e2.w*h5;
            yo = x - l0.z*s1 - l0.w*s2;
            s2 = s1; s1 = yo; o4.y = yo;
            h5 = h4; h4 = h3; h3 = h2; h2 = h1; h1 = h0; h0 = y4.y;

            // t+2 : Ae = e3.xyzw, e4.xy ; Al = l1.xy
            x  = y4.z + e3.x*h0 + e3.y*h1 + e3.z*h2 + e3.w*h3 + e4.x*h4 + e4.y*h5;
            yo = x - l1.x*s1 - l1.y*s2;
            s2 = s1; s1 = yo; o4.z = yo;
            h5 = h4; h4 = h3; h3 = h2; h2 = h1; h1 = h0; h0 = y4.z;

            // t+3 : Ae = e4.zw, e5.xyzw ; Al = l1.zw
            x  = y4.w + e4.z*h0 + e4.w*h1 + e5.x*h2 + e5.y*h3 + e5.z*h4 + e5.w*h5;
            yo = x - l1.z*s1 - l1.w*s2;
            s2 = s1; s1 = yo; o4.w = yo;
            h5 = h4; h4 = h3; h3 = h2; h2 = h1; h1 = h0; h0 = y4.w;

            if (t >= start && t < TLEN) {
                *reinterpret_cast<float4*>(ob + t) = o4;
            }
        }
    }
}

extern "C" void kernel_launch(void* const* d_in, const int* in_sizes, int n_in,
                              void* d_out, int out_size)
{
    const float* y  = (const float*)d_in[0];
    const float* Ae = (const float*)d_in[1];
    const float* Al = (const float*)d_in[2];
    float* out = (float*)d_out;

    cudaFuncSetAttribute(diffks_kernel,
                         cudaFuncAttributeMaxDynamicSharedMemorySize, SMEM_BYTES);

    diffks_kernel<<<BATCH * BPR, CPB, SMEM_BYTES>>>(y, Ae, Al, out);
}